// round 5
// baseline (speedup 1.0000x reference)
#include <cuda_runtime.h>
#include <stdint.h>

#define NN   50000
#define EE   800000
#define INF  128
#define OUTF 64
#define HEADS 4
#define OUT_COLS 256
#define NEG_SLOPE 0.2f
#define EPSV 1e-8f
#define NB_SCAN 49

// ---------------- scratch ----------------
__device__ __align__(16) float g_Wh[(size_t)NN * OUT_COLS];   // [n][h*64+f] 51.2 MB
__device__ __align__(16) float g_WtT[OUT_COLS * INF];         // [n][k] transposed weights
__device__ __align__(16) float4 g_p4s[INF];   // folded a_src:  p[k].h
__device__ __align__(16) float4 g_p4d[INF];   // folded a_dst
__device__ __align__(16) float4 g_es4[NN];
__device__ __align__(16) float4 g_ed4[NN];
__device__ __align__(16) float4 g_rinv4[NN];
__device__ __align__(16) float4 g_att4[EE];
__device__ int g_cnt[NN];
__device__ int g_rowptr[NN];
__device__ int g_cursor[NN];
__device__ int g_srcs[EE];
__device__ int g_bsum[64];

__device__ __forceinline__ uint32_t f2tf32(float f) {
    uint32_t r;
    asm("cvt.rna.tf32.f32 %0, %1;" : "=r"(r) : "f"(f));
    return r;
}

__device__ __forceinline__ void mma_tf32(float* c, const uint32_t* a, const uint32_t* b) {
    asm volatile("mma.sync.aligned.m16n8k8.row.col.f32.tf32.tf32.f32 "
        "{%0,%1,%2,%3}, {%4,%5,%6,%7}, {%8,%9}, {%0,%1,%2,%3};"
        : "+f"(c[0]), "+f"(c[1]), "+f"(c[2]), "+f"(c[3])
        : "r"(a[0]), "r"(a[1]), "r"(a[2]), "r"(a[3]), "r"(b[0]), "r"(b[1]));
}

// ---------------- init: zero histogram ----------------
__global__ void init_kernel() {
    int i = blockIdx.x * blockDim.x + threadIdx.x;
    if (i < NN) g_cnt[i] = 0;
}

// ---------------- prep: transpose W -> WtT[n][k]; fold a into p vectors ----------------
__global__ void prep_kernel(const float* __restrict__ W,
                            const float* __restrict__ a_src,
                            const float* __restrict__ a_dst) {
    int t = threadIdx.x;  // 512 threads, 1 block
    for (int idx = t; idx < OUT_COLS * INF; idx += 512) {
        int n = idx >> 7, k = idx & 127;
        int h = n >> 6, f = n & 63;
        g_WtT[idx] = W[((size_t)h * INF + k) * OUTF + f];
    }
    // p[k].h = sum_f W[h][k][f] * a[h][f];  t = k*4 + h
    int k = t >> 2, h = t & 3;
    const float* wr = W + ((size_t)h * INF + k) * OUTF;
    const float* as = a_src + h * OUTF;
    const float* ad = a_dst + h * OUTF;
    float ss = 0.f, dd = 0.f;
#pragma unroll 16
    for (int f = 0; f < OUTF; f++) { float w = wr[f]; ss += w * as[f]; dd += w * ad[f]; }
    reinterpret_cast<float*>(g_p4s)[k * 4 + h] = ss;
    reinterpret_cast<float*>(g_p4d)[k * 4 + h] = dd;
}

// ---------------- tf32 tensor-core GEMM: Wh = x @ WtT^T  (M=50000, N=256, K=128) ----------------
#define BM 128
#define BN 128
#define BK 32
#define SAS 36   // smem row stride (floats): bank = const + lane -> conflict-free

__global__ __launch_bounds__(512) void gemm_tf32_kernel(const float* __restrict__ x) {
    __shared__ uint32_t As[BM][SAS];
    __shared__ uint32_t Bs[BN][SAS];
    int tid = threadIdx.x;
    int wid = tid >> 5, lane = tid & 31;
    int wm = wid & 3, wn = wid >> 2;     // 4x4 warp grid, warp tile 32x32
    int row0 = blockIdx.x * BM;
    int col0 = blockIdx.y * BN;
    int lq = lane >> 2;                  // lane/4
    int lr = lane & 3;                   // lane%4

    float c[2][4][4];
#pragma unroll
    for (int mt = 0; mt < 2; mt++)
#pragma unroll
        for (int nt = 0; nt < 4; nt++)
#pragma unroll
            for (int r = 0; r < 4; r++) c[mt][nt][r] = 0.f;

    for (int kt = 0; kt < 4; kt++) {
#pragma unroll
        for (int j = 0; j < 2; j++) {            // fill A (128x32)
            int lin = tid + 512 * j;             // float4 id
            int r = lin >> 3, c4 = lin & 7;
            int gr = row0 + r;
            float4 v = make_float4(0.f, 0.f, 0.f, 0.f);
            if (gr < NN)
                v = *reinterpret_cast<const float4*>(x + (size_t)gr * INF + kt * BK + c4 * 4);
            uint32_t* dst = &As[r][c4 * 4];
            dst[0] = f2tf32(v.x); dst[1] = f2tf32(v.y);
            dst[2] = f2tf32(v.z); dst[3] = f2tf32(v.w);
        }
#pragma unroll
        for (int j = 0; j < 2; j++) {            // fill B (128x32) from WtT
            int lin = tid + 512 * j;
            int r = lin >> 3, c4 = lin & 7;
            float4 v = *reinterpret_cast<const float4*>(
                g_WtT + (size_t)(col0 + r) * INF + kt * BK + c4 * 4);
            uint32_t* dst = &Bs[r][c4 * 4];
            dst[0] = f2tf32(v.x); dst[1] = f2tf32(v.y);
            dst[2] = f2tf32(v.z); dst[3] = f2tf32(v.w);
        }
        __syncthreads();

#pragma unroll
        for (int ks = 0; ks < 4; ks++) {
            int kk = ks * 8;
            uint32_t a[2][4], b[4][2];
#pragma unroll
            for (int mt = 0; mt < 2; mt++) {
                int rb = wm * 32 + mt * 16 + lq;
                a[mt][0] = As[rb][kk + lr];
                a[mt][1] = As[rb + 8][kk + lr];
                a[mt][2] = As[rb][kk + 4 + lr];
                a[mt][3] = As[rb + 8][kk + 4 + lr];
            }
#pragma unroll
            for (int nt = 0; nt < 4; nt++) {
                int nb = wn * 32 + nt * 8 + lq;
                b[nt][0] = Bs[nb][kk + lr];
                b[nt][1] = Bs[nb][kk + 4 + lr];
            }
#pragma unroll
            for (int mt = 0; mt < 2; mt++)
#pragma unroll
                for (int nt = 0; nt < 4; nt++)
                    mma_tf32(c[mt][nt], a[mt], b[nt]);
        }
        __syncthreads();
    }

#pragma unroll
    for (int mt = 0; mt < 2; mt++) {
        int r0 = row0 + wm * 32 + mt * 16 + lq;
#pragma unroll
        for (int nt = 0; nt < 4; nt++) {
            int cc = col0 + wn * 32 + nt * 8 + lr * 2;
            if (r0 < NN)
                *reinterpret_cast<float2*>(g_Wh + (size_t)r0 * OUT_COLS + cc) =
                    make_float2(c[mt][nt][0], c[mt][nt][1]);
            if (r0 + 8 < NN)
                *reinterpret_cast<float2*>(g_Wh + (size_t)(r0 + 8) * OUT_COLS + cc) =
                    make_float2(c[mt][nt][2], c[mt][nt][3]);
        }
    }
}

// ---------------- logits straight from x (fp32-exact): warp per node ----------------
__global__ void logit_kernel(const float* __restrict__ x) {
    int n = (blockIdx.x * blockDim.x + threadIdx.x) >> 5;
    int lane = threadIdx.x & 31;
    if (n >= NN) return;
    float4 xv = *reinterpret_cast<const float4*>(x + (size_t)n * INF + lane * 4);
    float xs[4] = {xv.x, xv.y, xv.z, xv.w};
    float4 s = make_float4(0.f, 0.f, 0.f, 0.f);
    float4 d = make_float4(0.f, 0.f, 0.f, 0.f);
#pragma unroll
    for (int j = 0; j < 4; j++) {
        int k = lane * 4 + j;
        float4 ps = g_p4s[k], pd = g_p4d[k];
        s.x = fmaf(xs[j], ps.x, s.x); s.y = fmaf(xs[j], ps.y, s.y);
        s.z = fmaf(xs[j], ps.z, s.z); s.w = fmaf(xs[j], ps.w, s.w);
        d.x = fmaf(xs[j], pd.x, d.x); d.y = fmaf(xs[j], pd.y, d.y);
        d.z = fmaf(xs[j], pd.z, d.z); d.w = fmaf(xs[j], pd.w, d.w);
    }
#pragma unroll
    for (int o = 16; o; o >>= 1) {
        s.x += __shfl_xor_sync(0xffffffffu, s.x, o);
        s.y += __shfl_xor_sync(0xffffffffu, s.y, o);
        s.z += __shfl_xor_sync(0xffffffffu, s.z, o);
        s.w += __shfl_xor_sync(0xffffffffu, s.w, o);
        d.x += __shfl_xor_sync(0xffffffffu, d.x, o);
        d.y += __shfl_xor_sync(0xffffffffu, d.y, o);
        d.z += __shfl_xor_sync(0xffffffffu, d.z, o);
        d.w += __shfl_xor_sync(0xffffffffu, d.w, o);
    }
    if (lane == 0) { g_es4[n] = s; g_ed4[n] = d; }
}

// ---------------- CSR build ----------------
__global__ void hist_kernel(const int* __restrict__ ei) {
    int e = blockIdx.x * blockDim.x + threadIdx.x;
    if (e >= EE) return;
    int d = ei[EE + e];
    if ((unsigned)d < NN) atomicAdd(&g_cnt[d], 1);
}

__global__ void scan_block_kernel() {
    __shared__ int sh[1024];
    int i = blockIdx.x * 1024 + threadIdx.x;
    int v = (i < NN) ? g_cnt[i] : 0;
    sh[threadIdx.x] = v;
    __syncthreads();
#pragma unroll
    for (int off = 1; off < 1024; off <<= 1) {
        int t = (threadIdx.x >= off) ? sh[threadIdx.x - off] : 0;
        __syncthreads();
        sh[threadIdx.x] += t;
        __syncthreads();
    }
    if (i < NN) g_rowptr[i] = sh[threadIdx.x] - v;
    if (threadIdx.x == 1023) g_bsum[blockIdx.x] = sh[1023];
}

__global__ void scan_bsum_kernel() {
    __shared__ int sh[64];
    int t = threadIdx.x;
    int v = (t < NB_SCAN) ? g_bsum[t] : 0;
    sh[t] = v;
    __syncthreads();
#pragma unroll
    for (int off = 1; off < 64; off <<= 1) {
        int u = (t >= off) ? sh[t - off] : 0;
        __syncthreads();
        sh[t] += u;
        __syncthreads();
    }
    if (t < NB_SCAN) g_bsum[t] = sh[t] - v;
}

__global__ void scan_add_kernel() {
    int i = blockIdx.x * blockDim.x + threadIdx.x;
    if (i >= NN) return;
    int r = g_rowptr[i] + g_bsum[i >> 10];
    g_rowptr[i] = r;
    g_cursor[i] = r;
}

__global__ void scatter_kernel(const int* __restrict__ ei) {
    int e = blockIdx.x * blockDim.x + threadIdx.x;
    if (e >= EE) return;
    int s = ei[e];
    int d = ei[EE + e];
    if ((unsigned)s >= NN || (unsigned)d >= NN) return;
    int pos = atomicAdd(&g_cursor[d], 1);
    g_srcs[pos] = s;
}

// ---------------- per-node softmax stats ----------------
__device__ __forceinline__ float4 leaky4(float4 a, float4 b) {
    float4 t = make_float4(a.x + b.x, a.y + b.y, a.z + b.z, a.w + b.w);
    t.x = t.x > 0.f ? t.x : t.x * NEG_SLOPE;
    t.y = t.y > 0.f ? t.y : t.y * NEG_SLOPE;
    t.z = t.z > 0.f ? t.z : t.z * NEG_SLOPE;
    t.w = t.w > 0.f ? t.w : t.w * NEG_SLOPE;
    return t;
}

__global__ void stats_kernel() {
    int n = (blockIdx.x * blockDim.x + threadIdx.x) >> 5;
    int lane = threadIdx.x & 31;
    if (n >= NN) return;
    int base = g_rowptr[n];
    int deg  = g_cnt[n];
    float4 ed = g_ed4[n];

    float4 m = make_float4(0.f, 0.f, 0.f, 0.f);
    for (int i = lane; i < deg; i += 32) {
        int s = g_srcs[base + i];
        float4 t = leaky4(g_es4[s], ed);
        m.x = fmaxf(m.x, t.x); m.y = fmaxf(m.y, t.y);
        m.z = fmaxf(m.z, t.z); m.w = fmaxf(m.w, t.w);
    }
#pragma unroll
    for (int o = 16; o; o >>= 1) {
        m.x = fmaxf(m.x, __shfl_xor_sync(0xffffffffu, m.x, o));
        m.y = fmaxf(m.y, __shfl_xor_sync(0xffffffffu, m.y, o));
        m.z = fmaxf(m.z, __shfl_xor_sync(0xffffffffu, m.z, o));
        m.w = fmaxf(m.w, __shfl_xor_sync(0xffffffffu, m.w, o));
    }
    float4 sum = make_float4(0.f, 0.f, 0.f, 0.f);
    for (int i = lane; i < deg; i += 32) {
        int s = g_srcs[base + i];
        float4 t = leaky4(g_es4[s], ed);
        float4 w = make_float4(__expf(t.x - m.x), __expf(t.y - m.y),
                               __expf(t.z - m.z), __expf(t.w - m.w));
        g_att4[base + i] = w;
        sum.x += w.x; sum.y += w.y; sum.z += w.z; sum.w += w.w;
    }
#pragma unroll
    for (int o = 16; o; o >>= 1) {
        sum.x += __shfl_xor_sync(0xffffffffu, sum.x, o);
        sum.y += __shfl_xor_sync(0xffffffffu, sum.y, o);
        sum.z += __shfl_xor_sync(0xffffffffu, sum.z, o);
        sum.w += __shfl_xor_sync(0xffffffffu, sum.w, o);
    }
    if (lane == 0) {
        g_rinv4[n] = make_float4(1.f / (sum.x + EPSV), 1.f / (sum.y + EPSV),
                                 1.f / (sum.z + EPSV), 1.f / (sum.w + EPSV));
    }
}

// ---------------- aggregate: warp per dst node, register accumulation ----------------
__global__ void agg_kernel(float* __restrict__ out) {
    int n = (blockIdx.x * blockDim.x + threadIdx.x) >> 5;
    int lane = threadIdx.x & 31;
    if (n >= NN) return;
    int base = g_rowptr[n];
    int deg  = g_cnt[n];

    float4 a0 = make_float4(0.f, 0.f, 0.f, 0.f);
    float4 a1 = make_float4(0.f, 0.f, 0.f, 0.f);
    bool hi = lane >= 16;

    for (int i = 0; i < deg; i++) {
        int s = g_srcs[base + i];
        float4 w4 = g_att4[base + i];
        float wa = hi ? w4.y : w4.x;
        float wb = hi ? w4.w : w4.z;
        const float4* row = reinterpret_cast<const float4*>(g_Wh + (size_t)s * OUT_COLS);
        float4 v0 = row[lane];
        float4 v1 = row[32 + lane];
        a0.x = fmaf(wa, v0.x, a0.x); a0.y = fmaf(wa, v0.y, a0.y);
        a0.z = fmaf(wa, v0.z, a0.z); a0.w = fmaf(wa, v0.w, a0.w);
        a1.x = fmaf(wb, v1.x, a1.x); a1.y = fmaf(wb, v1.y, a1.y);
        a1.z = fmaf(wb, v1.z, a1.z); a1.w = fmaf(wb, v1.w, a1.w);
    }
    float4 r = g_rinv4[n];
    float ra = hi ? r.y : r.x;
    float rb = hi ? r.w : r.z;
    a0.x *= ra; a0.y *= ra; a0.z *= ra; a0.w *= ra;
    a1.x *= rb; a1.y *= rb; a1.z *= rb; a1.w *= rb;
    float4* orow = reinterpret_cast<float4*>(out + (size_t)n * OUT_COLS);
    orow[lane] = a0;
    orow[32 + lane] = a1;
}

// ---------------- launch ----------------
extern "C" void kernel_launch(void* const* d_in, const int* in_sizes, int n_in,
                              void* d_out, int out_size) {
    const float* x     = nullptr;
    const int*   ei    = nullptr;
    const float* W     = nullptr;
    const float* a_src = nullptr;
    const float* a_dst = nullptr;
    for (int i = 0; i < n_in; i++) {
        int sz = in_sizes[i];
        if      (sz == NN * INF)            x  = (const float*)d_in[i];
        else if (sz == 2 * EE)              ei = (const int*)d_in[i];
        else if (sz == HEADS * INF * OUTF)  W  = (const float*)d_in[i];
        else if (sz == HEADS * OUTF) {
            if (!a_src) a_src = (const float*)d_in[i];
            else        a_dst = (const float*)d_in[i];
        }
    }
    float* out = (float*)d_out;
    (void)out_size;

    init_kernel<<<(NN + 255) / 256, 256>>>();
    prep_kernel<<<1, 512>>>(W, a_src, a_dst);
    {
        dim3 grid((NN + BM - 1) / BM, OUT_COLS / BN);
        gemm_tf32_kernel<<<grid, 512>>>(x);
    }
    logit_kernel<<<((size_t)NN * 32 + 255) / 256, 256>>>(x);
    hist_kernel<<<(EE + 255) / 256, 256>>>(ei);
    scan_block_kernel<<<NB_SCAN, 1024>>>();
    scan_bsum_kernel<<<1, 64>>>();
    scan_add_kernel<<<(NN + 255) / 256, 256>>>();
    scatter_kernel<<<(EE + 255) / 256, 256>>>(ei);
    stats_kernel<<<((size_t)NN * 32 + 255) / 256, 256>>>();
    agg_kernel<<<((size_t)NN * 32 + 255) / 256, 256>>>(out);
}

// round 6
// speedup vs baseline: 1.0523x; 1.0523x over previous
#include <cuda_runtime.h>
#include <cuda_fp16.h>
#include <stdint.h>

#define NN   50000
#define EE   800000
#define INF  128
#define OUTF 64
#define HEADS 4
#define OUT_COLS 256
#define NEG_SLOPE 0.2f
#define EPSV 1e-8f
#define NB_SCAN 49

// ---------------- scratch ----------------
__device__ __align__(16) __half g_Wh[(size_t)NN * OUT_COLS];  // [n][h*64+f] fp16, 25.6 MB
__device__ __align__(16) float g_WtT[OUT_COLS * INF];         // [n][k] transposed weights
__device__ __align__(16) float4 g_p4s[INF];
__device__ __align__(16) float4 g_p4d[INF];
__device__ __align__(16) float4 g_es4[NN];
__device__ __align__(16) float4 g_ed4[NN];
__device__ __align__(16) float4 g_rinv4[NN];
__device__ __align__(16) float4 g_att4[EE];
__device__ int g_cnt[NN];
__device__ int g_rowptr[NN];
__device__ int g_cursor[NN];
__device__ int g_srcs[EE];
__device__ int g_bsum[64];

__device__ __forceinline__ uint32_t f2tf32(float f) {
    uint32_t r;
    asm("cvt.rna.tf32.f32 %0, %1;" : "=r"(r) : "f"(f));
    return r;
}

__device__ __forceinline__ void mma_tf32(float* c, const uint32_t* a, const uint32_t* b) {
    asm volatile("mma.sync.aligned.m16n8k8.row.col.f32.tf32.tf32.f32 "
        "{%0,%1,%2,%3}, {%4,%5,%6,%7}, {%8,%9}, {%0,%1,%2,%3};"
        : "+f"(c[0]), "+f"(c[1]), "+f"(c[2]), "+f"(c[3])
        : "r"(a[0]), "r"(a[1]), "r"(a[2]), "r"(a[3]), "r"(b[0]), "r"(b[1]));
}

// ---------------- init ----------------
__global__ void init_kernel() {
    int i = blockIdx.x * blockDim.x + threadIdx.x;
    if (i < NN) g_cnt[i] = 0;
}

// ---------------- prep: W -> WtT[n][k]; fold a into p vectors ----------------
__global__ void prep_kernel(const float* __restrict__ W,
                            const float* __restrict__ a_src,
                            const float* __restrict__ a_dst) {
    int t = threadIdx.x;  // 512 threads, 1 block
    for (int idx = t; idx < OUT_COLS * INF; idx += 512) {
        int n = idx >> 7, k = idx & 127;
        int h = n >> 6, f = n & 63;
        g_WtT[idx] = W[((size_t)h * INF + k) * OUTF + f];
    }
    int k = t >> 2, h = t & 3;
    const float* wr = W + ((size_t)h * INF + k) * OUTF;
    const float* as = a_src + h * OUTF;
    const float* ad = a_dst + h * OUTF;
    float ss = 0.f, dd = 0.f;
#pragma unroll 16
    for (int f = 0; f < OUTF; f++) { float w = wr[f]; ss += w * as[f]; dd += w * ad[f]; }
    reinterpret_cast<float*>(g_p4s)[k * 4 + h] = ss;
    reinterpret_cast<float*>(g_p4d)[k * 4 + h] = dd;
}

// ---------------- tf32 GEMM: Wh(fp16) = x @ WtT^T ----------------
#define BM 128
#define BN 128
#define BK 32
#define SAS 36

__global__ __launch_bounds__(512) void gemm_tf32_kernel(const float* __restrict__ x) {
    __shared__ uint32_t As[BM][SAS];
    __shared__ uint32_t Bs[BN][SAS];
    int tid = threadIdx.x;
    int wid = tid >> 5, lane = tid & 31;
    int wm = wid & 3, wn = wid >> 2;
    int row0 = blockIdx.x * BM;
    int col0 = blockIdx.y * BN;
    int lq = lane >> 2;
    int lr = lane & 3;

    float c[2][4][4];
#pragma unroll
    for (int mt = 0; mt < 2; mt++)
#pragma unroll
        for (int nt = 0; nt < 4; nt++)
#pragma unroll
            for (int r = 0; r < 4; r++) c[mt][nt][r] = 0.f;

    for (int kt = 0; kt < 4; kt++) {
#pragma unroll
        for (int j = 0; j < 2; j++) {
            int lin = tid + 512 * j;
            int r = lin >> 3, c4 = lin & 7;
            int gr = row0 + r;
            float4 v = make_float4(0.f, 0.f, 0.f, 0.f);
            if (gr < NN)
                v = *reinterpret_cast<const float4*>(x + (size_t)gr * INF + kt * BK + c4 * 4);
            uint32_t* dst = &As[r][c4 * 4];
            dst[0] = f2tf32(v.x); dst[1] = f2tf32(v.y);
            dst[2] = f2tf32(v.z); dst[3] = f2tf32(v.w);
        }
#pragma unroll
        for (int j = 0; j < 2; j++) {
            int lin = tid + 512 * j;
            int r = lin >> 3, c4 = lin & 7;
            float4 v = *reinterpret_cast<const float4*>(
                g_WtT + (size_t)(col0 + r) * INF + kt * BK + c4 * 4);
            uint32_t* dst = &Bs[r][c4 * 4];
            dst[0] = f2tf32(v.x); dst[1] = f2tf32(v.y);
            dst[2] = f2tf32(v.z); dst[3] = f2tf32(v.w);
        }
        __syncthreads();

#pragma unroll
        for (int ks = 0; ks < 4; ks++) {
            int kk = ks * 8;
            uint32_t a[2][4], b[4][2];
#pragma unroll
            for (int mt = 0; mt < 2; mt++) {
                int rb = wm * 32 + mt * 16 + lq;
                a[mt][0] = As[rb][kk + lr];
                a[mt][1] = As[rb + 8][kk + lr];
                a[mt][2] = As[rb][kk + 4 + lr];
                a[mt][3] = As[rb + 8][kk + 4 + lr];
            }
#pragma unroll
            for (int nt = 0; nt < 4; nt++) {
                int nb = wn * 32 + nt * 8 + lq;
                b[nt][0] = Bs[nb][kk + lr];
                b[nt][1] = Bs[nb][kk + 4 + lr];
            }
#pragma unroll
            for (int mt = 0; mt < 2; mt++)
#pragma unroll
                for (int nt = 0; nt < 4; nt++)
                    mma_tf32(c[mt][nt], a[mt], b[nt]);
        }
        __syncthreads();
    }

#pragma unroll
    for (int mt = 0; mt < 2; mt++) {
        int r0 = row0 + wm * 32 + mt * 16 + lq;
#pragma unroll
        for (int nt = 0; nt < 4; nt++) {
            int cc = col0 + wn * 32 + nt * 8 + lr * 2;
            if (r0 < NN)
                *reinterpret_cast<__half2*>(g_Wh + (size_t)r0 * OUT_COLS + cc) =
                    __floats2half2_rn(c[mt][nt][0], c[mt][nt][1]);
            if (r0 + 8 < NN)
                *reinterpret_cast<__half2*>(g_Wh + (size_t)(r0 + 8) * OUT_COLS + cc) =
                    __floats2half2_rn(c[mt][nt][2], c[mt][nt][3]);
        }
    }
}

// ---------------- logits from x (fp32-exact), p staged in smem ----------------
__global__ __launch_bounds__(256) void logit_kernel(const float* __restrict__ x) {
    __shared__ float4 sp[256];   // [0..127]=p_src, [128..255]=p_dst
    if (threadIdx.x < 256)
        sp[threadIdx.x] = (threadIdx.x < 128) ? g_p4s[threadIdx.x]
                                              : g_p4d[threadIdx.x - 128];
    __syncthreads();
    int n = (blockIdx.x * blockDim.x + threadIdx.x) >> 5;
    int lane = threadIdx.x & 31;
    if (n >= NN) return;
    float4 xv = *reinterpret_cast<const float4*>(x + (size_t)n * INF + lane * 4);
    float xs[4] = {xv.x, xv.y, xv.z, xv.w};
    float4 s = make_float4(0.f, 0.f, 0.f, 0.f);
    float4 d = make_float4(0.f, 0.f, 0.f, 0.f);
#pragma unroll
    for (int j = 0; j < 4; j++) {
        int k = lane * 4 + j;
        float4 ps = sp[k], pd = sp[128 + k];
        s.x = fmaf(xs[j], ps.x, s.x); s.y = fmaf(xs[j], ps.y, s.y);
        s.z = fmaf(xs[j], ps.z, s.z); s.w = fmaf(xs[j], ps.w, s.w);
        d.x = fmaf(xs[j], pd.x, d.x); d.y = fmaf(xs[j], pd.y, d.y);
        d.z = fmaf(xs[j], pd.z, d.z); d.w = fmaf(xs[j], pd.w, d.w);
    }
#pragma unroll
    for (int o = 16; o; o >>= 1) {
        s.x += __shfl_xor_sync(0xffffffffu, s.x, o);
        s.y += __shfl_xor_sync(0xffffffffu, s.y, o);
        s.z += __shfl_xor_sync(0xffffffffu, s.z, o);
        s.w += __shfl_xor_sync(0xffffffffu, s.w, o);
        d.x += __shfl_xor_sync(0xffffffffu, d.x, o);
        d.y += __shfl_xor_sync(0xffffffffu, d.y, o);
        d.z += __shfl_xor_sync(0xffffffffu, d.z, o);
        d.w += __shfl_xor_sync(0xffffffffu, d.w, o);
    }
    if (lane == 0) { g_es4[n] = s; g_ed4[n] = d; }
}

// ---------------- CSR build ----------------
__global__ void hist_kernel(const int* __restrict__ ei) {
    int e = blockIdx.x * blockDim.x + threadIdx.x;
    if (e >= EE) return;
    int d = ei[EE + e];
    if ((unsigned)d < NN) atomicAdd(&g_cnt[d], 1);
}

__global__ void scan_block_kernel() {
    __shared__ int sh[1024];
    int i = blockIdx.x * 1024 + threadIdx.x;
    int v = (i < NN) ? g_cnt[i] : 0;
    sh[threadIdx.x] = v;
    __syncthreads();
#pragma unroll
    for (int off = 1; off < 1024; off <<= 1) {
        int t = (threadIdx.x >= off) ? sh[threadIdx.x - off] : 0;
        __syncthreads();
        sh[threadIdx.x] += t;
        __syncthreads();
    }
    if (i < NN) g_rowptr[i] = sh[threadIdx.x] - v;
    if (threadIdx.x == 1023) g_bsum[blockIdx.x] = sh[1023];
}

__global__ void scan_bsum_kernel() {
    __shared__ int sh[64];
    int t = threadIdx.x;
    int v = (t < NB_SCAN) ? g_bsum[t] : 0;
    sh[t] = v;
    __syncthreads();
#pragma unroll
    for (int off = 1; off < 64; off <<= 1) {
        int u = (t >= off) ? sh[t - off] : 0;
        __syncthreads();
        sh[t] += u;
        __syncthreads();
    }
    if (t < NB_SCAN) g_bsum[t] = sh[t] - v;
}

__global__ void scan_add_kernel() {
    int i = blockIdx.x * blockDim.x + threadIdx.x;
    if (i >= NN) return;
    int r = g_rowptr[i] + g_bsum[i >> 10];
    g_rowptr[i] = r;
    g_cursor[i] = r;
}

__global__ void scatter_kernel(const int* __restrict__ ei) {
    int e = blockIdx.x * blockDim.x + threadIdx.x;
    if (e >= EE) return;
    int s = ei[e];
    int d = ei[EE + e];
    if ((unsigned)s >= NN || (unsigned)d >= NN) return;
    int pos = atomicAdd(&g_cursor[d], 1);
    g_srcs[pos] = s;
}

// ---------------- softmax stats: pass1 caches t, pass2 streams it ----------------
__device__ __forceinline__ float4 leaky4(float4 a, float4 b) {
    float4 t = make_float4(a.x + b.x, a.y + b.y, a.z + b.z, a.w + b.w);
    t.x = t.x > 0.f ? t.x : t.x * NEG_SLOPE;
    t.y = t.y > 0.f ? t.y : t.y * NEG_SLOPE;
    t.z = t.z > 0.f ? t.z : t.z * NEG_SLOPE;
    t.w = t.w > 0.f ? t.w : t.w * NEG_SLOPE;
    return t;
}

__global__ void stats_kernel() {
    int n = (blockIdx.x * blockDim.x + threadIdx.x) >> 5;
    int lane = threadIdx.x & 31;
    if (n >= NN) return;
    int base = g_rowptr[n];
    int deg  = g_cnt[n];
    float4 ed = g_ed4[n];

    float4 m = make_float4(0.f, 0.f, 0.f, 0.f);
    for (int i = lane; i < deg; i += 32) {
        int s = g_srcs[base + i];
        float4 t = leaky4(g_es4[s], ed);
        g_att4[base + i] = t;    // cache logits
        m.x = fmaxf(m.x, t.x); m.y = fmaxf(m.y, t.y);
        m.z = fmaxf(m.z, t.z); m.w = fmaxf(m.w, t.w);
    }
#pragma unroll
    for (int o = 16; o; o >>= 1) {
        m.x = fmaxf(m.x, __shfl_xor_sync(0xffffffffu, m.x, o));
        m.y = fmaxf(m.y, __shfl_xor_sync(0xffffffffu, m.y, o));
        m.z = fmaxf(m.z, __shfl_xor_sync(0xffffffffu, m.z, o));
        m.w = fmaxf(m.w, __shfl_xor_sync(0xffffffffu, m.w, o));
    }
    float4 sum = make_float4(0.f, 0.f, 0.f, 0.f);
    for (int i = lane; i < deg; i += 32) {
        float4 t = g_att4[base + i];
        float4 w = make_float4(__expf(t.x - m.x), __expf(t.y - m.y),
                               __expf(t.z - m.z), __expf(t.w - m.w));
        g_att4[base + i] = w;
        sum.x += w.x; sum.y += w.y; sum.z += w.z; sum.w += w.w;
    }
#pragma unroll
    for (int o = 16; o; o >>= 1) {
        sum.x += __shfl_xor_sync(0xffffffffu, sum.x, o);
        sum.y += __shfl_xor_sync(0xffffffffu, sum.y, o);
        sum.z += __shfl_xor_sync(0xffffffffu, sum.z, o);
        sum.w += __shfl_xor_sync(0xffffffffu, sum.w, o);
    }
    if (lane == 0) {
        g_rinv4[n] = make_float4(1.f / (sum.x + EPSV), 1.f / (sum.y + EPSV),
                                 1.f / (sum.z + EPSV), 1.f / (sum.w + EPSV));
    }
}

// ---------------- aggregate: warp per dst, fp16 gather, fp32 accumulate ----------------
__global__ void agg_kernel(float* __restrict__ out) {
    int n = (blockIdx.x * blockDim.x + threadIdx.x) >> 5;
    int lane = threadIdx.x & 31;
    if (n >= NN) return;
    int base = g_rowptr[n];
    int deg  = g_cnt[n];
    int h = lane >> 3;     // lane covers cols [lane*8, lane*8+8), one head per lane

    float acc[8];
#pragma unroll
    for (int j = 0; j < 8; j++) acc[j] = 0.f;

    for (int i = 0; i < deg; i++) {
        int s = g_srcs[base + i];        // broadcast
        float4 w4 = g_att4[base + i];    // broadcast
        float w = (&w4.x)[h];
        uint4 v = reinterpret_cast<const uint4*>(g_Wh + (size_t)s * OUT_COLS)[lane];
        const __half2* hv = reinterpret_cast<const __half2*>(&v);
#pragma unroll
        for (int j = 0; j < 4; j++) {
            float2 f = __half22float2(hv[j]);
            acc[2 * j]     = fmaf(w, f.x, acc[2 * j]);
            acc[2 * j + 1] = fmaf(w, f.y, acc[2 * j + 1]);
        }
    }
    float4 rv = g_rinv4[n];
    float r = (&rv.x)[h];
    float4 o0 = make_float4(acc[0] * r, acc[1] * r, acc[2] * r, acc[3] * r);
    float4 o1 = make_float4(acc[4] * r, acc[5] * r, acc[6] * r, acc[7] * r);
    float4* orow = reinterpret_cast<float4*>(out + (size_t)n * OUT_COLS);
    orow[lane * 2]     = o0;
    orow[lane * 2 + 1] = o1;
}

// ---------------- launch ----------------
extern "C" void kernel_launch(void* const* d_in, const int* in_sizes, int n_in,
                              void* d_out, int out_size) {
    const float* x     = nullptr;
    const int*   ei    = nullptr;
    const float* W     = nullptr;
    const float* a_src = nullptr;
    const float* a_dst = nullptr;
    for (int i = 0; i < n_in; i++) {
        int sz = in_sizes[i];
        if      (sz == NN * INF)            x  = (const float*)d_in[i];
        else if (sz == 2 * EE)              ei = (const int*)d_in[i];
        else if (sz == HEADS * INF * OUTF)  W  = (const float*)d_in[i];
        else if (sz == HEADS * OUTF) {
            if (!a_src) a_src = (const float*)d_in[i];
            else        a_dst = (const float*)d_in[i];
        }
    }
    float* out = (float*)d_out;
    (void)out_size;

    init_kernel<<<(NN + 255) / 256, 256>>>();
    prep_kernel<<<1, 512>>>(W, a_src, a_dst);
    {
        dim3 grid((NN + BM - 1) / BM, OUT_COLS / BN);
        gemm_tf32_kernel<<<grid, 512>>>(x);
    }
    logit_kernel<<<((size_t)NN * 32 + 255) / 256, 256>>>(x);
    hist_kernel<<<(EE + 255) / 256, 256>>>(ei);
    scan_block_kernel<<<NB_SCAN, 1024>>>();
    scan_bsum_kernel<<<1, 64>>>();
    scan_add_kernel<<<(NN + 255) / 256, 256>>>();
    scatter_kernel<<<(EE + 255) / 256, 256>>>(ei);
    stats_kernel<<<((size_t)NN * 32 + 255) / 256, 256>>>();
    agg_kernel<<<((size_t)NN * 32 + 255) / 256, 256>>>(out);
}